// round 6
// baseline (speedup 1.0000x reference)
#include <cuda_runtime.h>
#include <cuda_bf16.h>
#include <math.h>

// Problem constants (from reference setup_inputs)
#define N 8192
#define D 128
#define MARGIN 0.3f

// Scratch (device globals -- allocation-free per harness rules)
__device__ float        g_sq[N];
__device__ unsigned int g_ap[N];   // float bits of hard-positive max (all dists >= 0)
__device__ unsigned int g_an[N];   // float bits of hard-negative min

// ---------------------------------------------------------------------------
// Kernel 1: row squared norms + init of ap/an scratch. One warp per row.
// ---------------------------------------------------------------------------
__global__ void sqnorm_kernel(const float* __restrict__ x) {
    int warp = (blockIdx.x * blockDim.x + threadIdx.x) >> 5;
    int lane = threadIdx.x & 31;
    if (warp >= N) return;
    const float4* xr = reinterpret_cast<const float4*>(x + (size_t)warp * D);
    float4 v = xr[lane];                       // 32 lanes x 4 = 128 elems
    float s = v.x * v.x + v.y * v.y + v.z * v.z + v.w * v.w;
    #pragma unroll
    for (int o = 16; o > 0; o >>= 1) s += __shfl_xor_sync(0xffffffffu, s, o);
    if (lane == 0) {
        g_sq[warp] = s;
        g_ap[warp] = 0u;            // 0.0f (diag always contributes dist 0)
        g_an[warp] = 0x7f800000u;   // +inf
    }
}

// ---------------------------------------------------------------------------
// Kernel 2: 64x64 distance tiles. 16x16 threads, 4x4 outputs per thread,
// k-chunks of 16 via float4 loads (X lives in L2: only 4 MB).
// Epilogue: dist = sqrt(max(sqi+sqj-2dot,0)); store; masked max/min reduce.
// ---------------------------------------------------------------------------
__global__ __launch_bounds__(256, 4)
void dist_kernel(const float* __restrict__ x, const int* __restrict__ tgt,
                 float* __restrict__ out) {
    __shared__ float As[16][64];
    __shared__ float Bs[16][64];
    __shared__ unsigned int sAp[64];
    __shared__ unsigned int sAn[64];

    const int tx = threadIdx.x;            // 0..15 -> cols
    const int ty = threadIdx.y;            // 0..15 -> rows
    const int t  = ty * 16 + tx;           // 0..255
    const int iBase = blockIdx.y * 64;
    const int jBase = blockIdx.x * 64;

    if (t < 64) { sAp[t] = 0u; sAn[t] = 0x7f800000u; }

    // load indices for the cooperative tile fill: 64 rows x 16 k per chunk
    const int lr = t >> 2;                 // 0..63
    const int lk = (t & 3) * 4;            // 0,4,8,12

    float acc[4][4];
    #pragma unroll
    for (int r = 0; r < 4; r++)
        #pragma unroll
        for (int c = 0; c < 4; c++) acc[r][c] = 0.f;

    #pragma unroll
    for (int kc = 0; kc < D; kc += 16) {
        float4 av = *reinterpret_cast<const float4*>(x + (size_t)(iBase + lr) * D + kc + lk);
        float4 bv = *reinterpret_cast<const float4*>(x + (size_t)(jBase + lr) * D + kc + lk);
        __syncthreads();                    // protect previous iteration reads
        As[lk + 0][lr] = av.x; As[lk + 1][lr] = av.y;
        As[lk + 2][lr] = av.z; As[lk + 3][lr] = av.w;
        Bs[lk + 0][lr] = bv.x; Bs[lk + 1][lr] = bv.y;
        Bs[lk + 2][lr] = bv.z; Bs[lk + 3][lr] = bv.w;
        __syncthreads();

        #pragma unroll
        for (int kk = 0; kk < 16; kk++) {
            float a[4], b[4];
            #pragma unroll
            for (int r = 0; r < 4; r++) a[r] = As[kk][ty * 4 + r];
            #pragma unroll
            for (int c = 0; c < 4; c++) b[c] = Bs[kk][tx * 4 + c];
            #pragma unroll
            for (int r = 0; r < 4; r++)
                #pragma unroll
                for (int c = 0; c < 4; c++) acc[r][c] = fmaf(a[r], b[c], acc[r][c]);
        }
    }

    // epilogue
    float sqi[4], sqj[4], apv[4], anv[4];
    int ti[4], tj[4];
    #pragma unroll
    for (int r = 0; r < 4; r++) {
        int row = iBase + ty * 4 + r;
        sqi[r] = g_sq[row];
        ti[r]  = tgt[row];
        apv[r] = 0.f;
        anv[r] = __int_as_float(0x7f800000);   // +inf
    }
    #pragma unroll
    for (int c = 0; c < 4; c++) {
        int col = jBase + tx * 4 + c;
        sqj[c] = g_sq[col];
        tj[c]  = tgt[col];
    }

    #pragma unroll
    for (int r = 0; r < 4; r++) {
        int row = iBase + ty * 4 + r;
        float* orow = out + (size_t)row * N + jBase + tx * 4;
        #pragma unroll
        for (int c = 0; c < 4; c++) {
            float sqd = sqi[r] + sqj[c] - 2.f * acc[r][c];
            float dd  = (sqd > 0.f) ? sqrtf(sqd) : 0.f;
            orow[c] = dd;
            if (ti[r] == tj[c]) apv[r] = fmaxf(apv[r], dd);
            else                anv[r] = fminf(anv[r], dd);
        }
    }

    __syncthreads();   // sAp/sAn init done (and smem tile reads finished)
    #pragma unroll
    for (int r = 0; r < 4; r++) {
        atomicMax(&sAp[ty * 4 + r], __float_as_uint(apv[r]));
        atomicMin(&sAn[ty * 4 + r], __float_as_uint(anv[r]));
    }
    __syncthreads();
    if (t < 64) {
        atomicMax(&g_ap[iBase + t], sAp[t]);
        atomicMin(&g_an[iBase + t], sAn[t]);
    }
}

// ---------------------------------------------------------------------------
// Kernel 3: loss = mean(relu(ap - an + margin)). Single block.
// ---------------------------------------------------------------------------
__global__ void loss_kernel(float* __restrict__ out) {
    __shared__ float red[32];
    float s = 0.f;
    for (int i = threadIdx.x; i < N; i += blockDim.x) {
        float ap = __uint_as_float(g_ap[i]);
        float an = __uint_as_float(g_an[i]);
        float v  = ap - an + MARGIN;
        s += (v > 0.f) ? v : 0.f;
    }
    #pragma unroll
    for (int o = 16; o > 0; o >>= 1) s += __shfl_xor_sync(0xffffffffu, s, o);
    int lane = threadIdx.x & 31, wid = threadIdx.x >> 5;
    if (lane == 0) red[wid] = s;
    __syncthreads();
    if (wid == 0) {
        s = (lane < (blockDim.x >> 5)) ? red[lane] : 0.f;
        #pragma unroll
        for (int o = 16; o > 0; o >>= 1) s += __shfl_xor_sync(0xffffffffu, s, o);
        if (lane == 0) out[0] = s / (float)N;
    }
}

// ---------------------------------------------------------------------------
extern "C" void kernel_launch(void* const* d_in, const int* in_sizes, int n_in,
                              void* d_out, int out_size) {
    const float* x   = (const float*)d_in[0];
    const int*   tgt = (const int*)d_in[1];
    float* out = (float*)d_out;           // out[0] = loss, out[1..] = dist

    // 1) row sq-norms + scratch init: 8 warps/block
    sqnorm_kernel<<<N / 8, 256>>>(x);

    // 2) distance tiles: 128x128 grid of 64x64 tiles
    dim3 grid(N / 64, N / 64), block(16, 16);
    dist_kernel<<<grid, block>>>(x, tgt, out + 1);

    // 3) loss reduction
    loss_kernel<<<1, 1024>>>(out);
}

// round 7
// speedup vs baseline: 1.0009x; 1.0009x over previous
#include <cuda_runtime.h>
#include <cuda_bf16.h>
#include <math.h>

// Problem constants (from reference setup_inputs)
#define N 8192
#define D 128
#define MARGIN 0.3f

// Scratch (device globals -- allocation-free per harness rules)
__device__ float        g_sq[N];
__device__ unsigned int g_ap[N];   // float bits of hard-positive max (all dists >= 0)
__device__ unsigned int g_an[N];   // float bits of hard-negative min

// ---------------------------------------------------------------------------
// Kernel 1: row squared norms + init of ap/an scratch. One warp per row.
// ---------------------------------------------------------------------------
__global__ void sqnorm_kernel(const float* __restrict__ x) {
    int warp = (blockIdx.x * blockDim.x + threadIdx.x) >> 5;
    int lane = threadIdx.x & 31;
    if (warp >= N) return;
    const float4* xr = reinterpret_cast<const float4*>(x + (size_t)warp * D);
    float4 v = xr[lane];                       // 32 lanes x 4 = 128 elems
    float s = v.x * v.x + v.y * v.y + v.z * v.z + v.w * v.w;
    #pragma unroll
    for (int o = 16; o > 0; o >>= 1) s += __shfl_xor_sync(0xffffffffu, s, o);
    if (lane == 0) {
        g_sq[warp] = s;
        g_ap[warp] = 0u;            // 0.0f (diag always contributes dist 0)
        g_an[warp] = 0x7f800000u;   // +inf
    }
}

// ---------------------------------------------------------------------------
// Kernel 2: 64x64 distance tiles. 16x16 threads, 4x4 outputs per thread,
// k-chunks of 16 via float4 loads (X lives in L2: only 4 MB).
// Epilogue: dist = sqrt(max(sqi+sqj-2dot,0)); store; masked max/min reduce.
// ---------------------------------------------------------------------------
__global__ __launch_bounds__(256, 4)
void dist_kernel(const float* __restrict__ x, const int* __restrict__ tgt,
                 float* __restrict__ out) {
    __shared__ float As[16][64];
    __shared__ float Bs[16][64];
    __shared__ unsigned int sAp[64];
    __shared__ unsigned int sAn[64];

    const int tx = threadIdx.x;            // 0..15 -> cols
    const int ty = threadIdx.y;            // 0..15 -> rows
    const int t  = ty * 16 + tx;           // 0..255
    const int iBase = blockIdx.y * 64;
    const int jBase = blockIdx.x * 64;

    if (t < 64) { sAp[t] = 0u; sAn[t] = 0x7f800000u; }

    // load indices for the cooperative tile fill: 64 rows x 16 k per chunk
    const int lr = t >> 2;                 // 0..63
    const int lk = (t & 3) * 4;            // 0,4,8,12

    float acc[4][4];
    #pragma unroll
    for (int r = 0; r < 4; r++)
        #pragma unroll
        for (int c = 0; c < 4; c++) acc[r][c] = 0.f;

    #pragma unroll
    for (int kc = 0; kc < D; kc += 16) {
        float4 av = *reinterpret_cast<const float4*>(x + (size_t)(iBase + lr) * D + kc + lk);
        float4 bv = *reinterpret_cast<const float4*>(x + (size_t)(jBase + lr) * D + kc + lk);
        __syncthreads();                    // protect previous iteration reads
        As[lk + 0][lr] = av.x; As[lk + 1][lr] = av.y;
        As[lk + 2][lr] = av.z; As[lk + 3][lr] = av.w;
        Bs[lk + 0][lr] = bv.x; Bs[lk + 1][lr] = bv.y;
        Bs[lk + 2][lr] = bv.z; Bs[lk + 3][lr] = bv.w;
        __syncthreads();

        #pragma unroll
        for (int kk = 0; kk < 16; kk++) {
            float a[4], b[4];
            #pragma unroll
            for (int r = 0; r < 4; r++) a[r] = As[kk][ty * 4 + r];
            #pragma unroll
            for (int c = 0; c < 4; c++) b[c] = Bs[kk][tx * 4 + c];
            #pragma unroll
            for (int r = 0; r < 4; r++)
                #pragma unroll
                for (int c = 0; c < 4; c++) acc[r][c] = fmaf(a[r], b[c], acc[r][c]);
        }
    }

    // epilogue
    float sqi[4], sqj[4], apv[4], anv[4];
    int ti[4], tj[4];
    #pragma unroll
    for (int r = 0; r < 4; r++) {
        int row = iBase + ty * 4 + r;
        sqi[r] = g_sq[row];
        ti[r]  = tgt[row];
        apv[r] = 0.f;
        anv[r] = __int_as_float(0x7f800000);   // +inf
    }
    #pragma unroll
    for (int c = 0; c < 4; c++) {
        int col = jBase + tx * 4 + c;
        sqj[c] = g_sq[col];
        tj[c]  = tgt[col];
    }

    #pragma unroll
    for (int r = 0; r < 4; r++) {
        int row = iBase + ty * 4 + r;
        float* orow = out + (size_t)row * N + jBase + tx * 4;
        #pragma unroll
        for (int c = 0; c < 4; c++) {
            float sqd = sqi[r] + sqj[c] - 2.f * acc[r][c];
            float dd  = (sqd > 0.f) ? sqrtf(sqd) : 0.f;
            orow[c] = dd;
            if (ti[r] == tj[c]) apv[r] = fmaxf(apv[r], dd);
            else                anv[r] = fminf(anv[r], dd);
        }
    }

    __syncthreads();   // sAp/sAn init done (and smem tile reads finished)
    #pragma unroll
    for (int r = 0; r < 4; r++) {
        atomicMax(&sAp[ty * 4 + r], __float_as_uint(apv[r]));
        atomicMin(&sAn[ty * 4 + r], __float_as_uint(anv[r]));
    }
    __syncthreads();
    if (t < 64) {
        atomicMax(&g_ap[iBase + t], sAp[t]);
        atomicMin(&g_an[iBase + t], sAn[t]);
    }
}

// ---------------------------------------------------------------------------
// Kernel 3: loss = mean(relu(ap - an + margin)). Single block.
// ---------------------------------------------------------------------------
__global__ void loss_kernel(float* __restrict__ out) {
    __shared__ float red[32];
    float s = 0.f;
    for (int i = threadIdx.x; i < N; i += blockDim.x) {
        float ap = __uint_as_float(g_ap[i]);
        float an = __uint_as_float(g_an[i]);
        float v  = ap - an + MARGIN;
        s += (v > 0.f) ? v : 0.f;
    }
    #pragma unroll
    for (int o = 16; o > 0; o >>= 1) s += __shfl_xor_sync(0xffffffffu, s, o);
    int lane = threadIdx.x & 31, wid = threadIdx.x >> 5;
    if (lane == 0) red[wid] = s;
    __syncthreads();
    if (wid == 0) {
        s = (lane < (blockDim.x >> 5)) ? red[lane] : 0.f;
        #pragma unroll
        for (int o = 16; o > 0; o >>= 1) s += __shfl_xor_sync(0xffffffffu, s, o);
        if (lane == 0) out[0] = s / (float)N;
    }
}

// ---------------------------------------------------------------------------
extern "C" void kernel_launch(void* const* d_in, const int* in_sizes, int n_in,
                              void* d_out, int out_size) {
    const float* x   = (const float*)d_in[0];
    const int*   tgt = (const int*)d_in[1];
    float* out = (float*)d_out;           // out[0] = loss, out[1..] = dist

    // 1) row sq-norms + scratch init: 8 warps/block
    sqnorm_kernel<<<N / 8, 256>>>(x);

    // 2) distance tiles: 128x128 grid of 64x64 tiles
    dim3 grid(N / 64, N / 64), block(16, 16);
    dist_kernel<<<grid, block>>>(x, tgt, out + 1);

    // 3) loss reduction
    loss_kernel<<<1, 1024>>>(out);
}